// round 4
// baseline (speedup 1.0000x reference)
#include <cuda_runtime.h>

#define NN 50000
#define EE 800000
#define DD 64

// Scratch (device globals — allocation-free per harness rules)
__device__ __align__(16) float g_agg1[NN * DD];
__device__ __align__(16) float g_agg2[NN * DD];
__device__ __align__(16) float g_h[NN * DD];
__device__ float g_cnt[NN];
__device__ int   g_src32[EE];
__device__ int   g_dst32[EE];
__device__ int   g_is64;

// ---------------------------------------------------------------------------
// Kernel 0: detect edge_index dtype. int64 layout => every odd 32-bit word is
// a zero high-word. int32 layout => odd words are random indices (~0 chance
// all 64 probes are zero).
// ---------------------------------------------------------------------------
__global__ void detect_kernel(const int* __restrict__ ei32) {
    int all_zero = 1;
    #pragma unroll 1
    for (int i = 0; i < 64; i++) {
        if (ei32[2 * i + 1] != 0) { all_zero = 0; break; }
    }
    g_is64 = all_zero;
}

// ---------------------------------------------------------------------------
// Kernel 1: zero accumulators + degree counts
// ---------------------------------------------------------------------------
__global__ __launch_bounds__(256) void zero_kernel() {
    int tid = blockIdx.x * blockDim.x + threadIdx.x;
    int stride = gridDim.x * blockDim.x;
    const int tot4 = (NN * DD) / 4;
    float4 z = make_float4(0.f, 0.f, 0.f, 0.f);
    for (int t = tid; t < tot4; t += stride) {
        reinterpret_cast<float4*>(g_agg1)[t] = z;
        reinterpret_cast<float4*>(g_agg2)[t] = z;
    }
    for (int t = tid; t < NN; t += stride) g_cnt[t] = 0.f;
}

// ---------------------------------------------------------------------------
// Kernel 2: normalize indices to int32 (dtype-agnostic) + degree histogram
// ---------------------------------------------------------------------------
__global__ __launch_bounds__(256) void convert_kernel(const void* __restrict__ ei) {
    int e = blockIdx.x * blockDim.x + threadIdx.x;
    if (e >= EE) return;
    int s, d;
    if (g_is64) {
        const long long* p = (const long long*)ei;
        s = (int)p[e];
        d = (int)p[EE + e];
    } else {
        const int* p = (const int*)ei;
        s = p[e];
        d = p[EE + e];
    }
    s = min(max(s, 0), NN - 1);
    d = min(max(d, 0), NN - 1);
    g_src32[e] = s;
    g_dst32[e] = d;
    atomicAdd(&g_cnt[d], 1.0f);
}

// ---------------------------------------------------------------------------
// Kernel 3/5: edge scatter. 16 threads per edge, one float4 each.
// Vector f32 reduction to L2 (red.global.add.v4.f32, sm_90+).
// ---------------------------------------------------------------------------
template <int LAYER>
__global__ __launch_bounds__(256) void scatter_kernel(const float* __restrict__ xext)
{
    int e = blockIdx.x * (256 / 16) + (threadIdx.x >> 4);
    if (e >= EE) return;
    int l = threadIdx.x & 15;

    int s = g_src32[e];
    int d = g_dst32[e];

    const float* xin = (LAYER == 1) ? xext : g_h;
    float*       agg = (LAYER == 1) ? g_agg1 : g_agg2;

    float4 v = *reinterpret_cast<const float4*>(xin + (size_t)s * DD + (l << 2));
    float* p = agg + (size_t)d * DD + (l << 2);
    asm volatile("red.global.add.v4.f32 [%0], {%1, %2, %3, %4};"
                 :: "l"(p), "f"(v.x), "f"(v.y), "f"(v.z), "f"(v.w)
                 : "memory");
}

// ---------------------------------------------------------------------------
// Kernel 4/6: fused per-node MLP:
//   out = (agg * 1/max(cnt,1)) @ W_l^T + b + xin @ W_r^T   [+ tanh, layer 1]
// W^T staged transposed in smem; 16 nodes/iter, 16 threads/node,
// 4 outputs/thread with LDS.128 weight reads.
// ---------------------------------------------------------------------------
template <int LAYER>
__global__ __launch_bounds__(256) void mlp_kernel(
    const float* __restrict__ xext,
    const float* __restrict__ Wl,
    const float* __restrict__ bl,
    const float* __restrict__ Wr,
    float* __restrict__ outext)
{
    const float* agg = (LAYER == 1) ? g_agg1 : g_agg2;
    const float* xin = (LAYER == 1) ? xext : g_h;
    float*       out = (LAYER == 1) ? g_h : outext;

    __shared__ float sWl[DD * DD];   // sWl[k*64 + j] = Wl[j*64 + k]
    __shared__ float sWr[DD * DD];
    __shared__ float sB[DD];
    __shared__ float sIn[16][2 * DD]; // per node: [agg row | x row]

    for (int t = threadIdx.x; t < DD * DD; t += 256) {
        int j = t >> 6, k = t & 63;
        sWl[(k << 6) + j] = Wl[t];
        sWr[(k << 6) + j] = Wr[t];
    }
    if (threadIdx.x < DD) sB[threadIdx.x] = bl[threadIdx.x];

    const int nloc = threadIdx.x >> 4;          // node slot 0..15
    const int j0   = (threadIdx.x & 15) << 2;   // output features j0..j0+3
    const int ngroups = (NN + 15) / 16;         // 3125

    for (int g = blockIdx.x; g < ngroups; g += gridDim.x) {
        int base = g << 4;
        __syncthreads();
        for (int t = threadIdx.x; t < 16 * 32; t += 256) {
            int node = t >> 5;
            int q    = t & 31;
            int ni   = base + node;
            float4 v = make_float4(0.f, 0.f, 0.f, 0.f);
            if (ni < NN) {
                v = (q < 16)
                    ? reinterpret_cast<const float4*>(agg + (size_t)ni * DD)[q]
                    : reinterpret_cast<const float4*>(xin + (size_t)ni * DD)[q - 16];
            }
            reinterpret_cast<float4*>(sIn[node])[q] = v;
        }
        __syncthreads();

        int ni = base + nloc;
        if (ni < NN) {
            const float* rA = sIn[nloc];
            const float* rX = sIn[nloc] + DD;
            float aL0 = 0.f, aL1 = 0.f, aL2 = 0.f, aL3 = 0.f;
            float aR0 = 0.f, aR1 = 0.f, aR2 = 0.f, aR3 = 0.f;
            #pragma unroll
            for (int k4 = 0; k4 < DD / 4; k4++) {
                float4 a4 = reinterpret_cast<const float4*>(rA)[k4];
                float4 x4 = reinterpret_cast<const float4*>(rX)[k4];
                #pragma unroll
                for (int kk = 0; kk < 4; kk++) {
                    int k   = k4 * 4 + kk;
                    float a  = (&a4.x)[kk];
                    float xv = (&x4.x)[kk];
                    float4 wl = *reinterpret_cast<const float4*>(sWl + (k << 6) + j0);
                    float4 wr = *reinterpret_cast<const float4*>(sWr + (k << 6) + j0);
                    aL0 += a * wl.x;  aL1 += a * wl.y;
                    aL2 += a * wl.z;  aL3 += a * wl.w;
                    aR0 += xv * wr.x; aR1 += xv * wr.y;
                    aR2 += xv * wr.z; aR3 += xv * wr.w;
                }
            }
            float inv = 1.0f / fmaxf(g_cnt[ni], 1.0f);
            float4 b4 = *reinterpret_cast<const float4*>(sB + j0);
            float4 o;
            o.x = aL0 * inv + b4.x + aR0;
            o.y = aL1 * inv + b4.y + aR1;
            o.z = aL2 * inv + b4.z + aR2;
            o.w = aL3 * inv + b4.w + aR3;
            if (LAYER == 1) {
                o.x = tanhf(o.x); o.y = tanhf(o.y);
                o.z = tanhf(o.z); o.w = tanhf(o.w);
            }
            *reinterpret_cast<float4*>(out + (size_t)ni * DD + j0) = o;
        }
    }
}

// ---------------------------------------------------------------------------
// Launch
// ---------------------------------------------------------------------------
extern "C" void kernel_launch(void* const* d_in, const int* in_sizes, int n_in,
                              void* d_out, int out_size)
{
    const float* x    = (const float*)d_in[0];
    const void*  ei   = d_in[1];
    const float* Wl1  = (const float*)d_in[2];
    const float* bl1  = (const float*)d_in[3];
    const float* Wr1  = (const float*)d_in[4];
    const float* Wl2  = (const float*)d_in[5];
    const float* bl2  = (const float*)d_in[6];
    const float* Wr2  = (const float*)d_in[7];
    float*       out  = (float*)d_out;

    const int scatter_blocks = EE / 16;   // 16 edges per 256-thread block
    const int mlp_blocks = 625;           // 3125 groups / 625 = 5 each

    detect_kernel<<<1, 1>>>((const int*)ei);
    zero_kernel<<<592, 256>>>();
    convert_kernel<<<(EE + 255) / 256, 256>>>(ei);
    scatter_kernel<1><<<scatter_blocks, 256>>>(x);
    mlp_kernel<1><<<mlp_blocks, 256>>>(x, Wl1, bl1, Wr1, nullptr);
    scatter_kernel<2><<<scatter_blocks, 256>>>(nullptr);
    mlp_kernel<2><<<mlp_blocks, 256>>>(nullptr, Wl2, bl2, Wr2, out);
}

// round 6
// speedup vs baseline: 1.1785x; 1.1785x over previous
#include <cuda_runtime.h>

#define NN 50000
#define EE 800000
#define DD 64

// Scratch (device globals — allocation-free per harness rules)
__device__ __align__(16) float g_agg[NN * DD];   // mean-aggregated features (reused both layers)
__device__ __align__(16) float g_h[NN * DD];     // layer-1 output
__device__ int g_src32[EE];
__device__ int g_dst32[EE];
__device__ int g_deg[NN];
__device__ int g_off[NN + 1];
__device__ int g_cur[NN];
__device__ int g_csr_src[EE];
__device__ int g_is64;

// ---------------------------------------------------------------------------
// Kernel 0: detect edge_index dtype (int64 => odd 32-bit words all zero).
// ---------------------------------------------------------------------------
__global__ void detect_kernel(const int* __restrict__ ei32) {
    int all_zero = 1;
    #pragma unroll 1
    for (int i = 0; i < 64; i++) {
        if (ei32[2 * i + 1] != 0) { all_zero = 0; break; }
    }
    g_is64 = all_zero;
}

// ---------------------------------------------------------------------------
// Kernel 1: zero degree counts
// ---------------------------------------------------------------------------
__global__ __launch_bounds__(256) void zero_deg_kernel() {
    int t = blockIdx.x * 256 + threadIdx.x;
    if (t < NN) g_deg[t] = 0;
}

// ---------------------------------------------------------------------------
// Kernel 2: normalize indices to int32 + integer degree histogram
// ---------------------------------------------------------------------------
__global__ __launch_bounds__(256) void convert_kernel(const void* __restrict__ ei) {
    int e = blockIdx.x * blockDim.x + threadIdx.x;
    if (e >= EE) return;
    int s, d;
    if (g_is64) {
        const long long* p = (const long long*)ei;
        s = (int)p[e];
        d = (int)p[EE + e];
    } else {
        const int* p = (const int*)ei;
        s = p[e];
        d = p[EE + e];
    }
    s = min(max(s, 0), NN - 1);
    d = min(max(d, 0), NN - 1);
    g_src32[e] = s;
    g_dst32[e] = d;
    atomicAdd(&g_deg[d], 1);
}

// ---------------------------------------------------------------------------
// Kernel 3: exclusive scan of g_deg -> g_off (single block, 1024 threads).
// Each thread owns a 49-element chunk; Hillis-Steele over the 1024 partials.
// ---------------------------------------------------------------------------
__global__ __launch_bounds__(1024) void scan_kernel() {
    const int CH = 49;  // 1024*49 = 50176 >= NN
    int tid = threadIdx.x;
    int start = tid * CH;
    int end = min(start + CH, NN);

    int s = 0;
    for (int i = start; i < end; i++) s += g_deg[i];

    __shared__ int part[1024];
    part[tid] = s;
    __syncthreads();
    for (int d = 1; d < 1024; d <<= 1) {
        int v = (tid >= d) ? part[tid - d] : 0;
        __syncthreads();
        part[tid] += v;
        __syncthreads();
    }
    int run = part[tid] - s;   // exclusive base for this chunk
    for (int i = start; i < end; i++) {
        g_off[i] = run;
        g_cur[i] = run;
        run += g_deg[i];
    }
    if (tid == 1023) g_off[NN] = EE;
}

// ---------------------------------------------------------------------------
// Kernel 4: CSR fill (source indices grouped by destination)
// ---------------------------------------------------------------------------
__global__ __launch_bounds__(256) void fill_kernel() {
    int e = blockIdx.x * blockDim.x + threadIdx.x;
    if (e >= EE) return;
    int d = g_dst32[e];
    int pos = atomicAdd(&g_cur[d], 1);
    g_csr_src[pos] = g_src32[e];
}

// ---------------------------------------------------------------------------
// Kernel 5/7: gather-based mean aggregation. One warp per node; lanes 0-15
// handle one edge's row (float4 each), lanes 16-31 the next edge. No atomics.
// Writes mean (already divided by max(deg,1)) into g_agg.
// ---------------------------------------------------------------------------
template <int LAYER>
__global__ __launch_bounds__(256) void gather_kernel(const float* __restrict__ xext)
{
    int n = (blockIdx.x * 256 + threadIdx.x) >> 5;
    if (n >= NN) return;
    int lane = threadIdx.x & 31;
    int half = lane >> 4;        // 0 or 1
    int fl   = lane & 15;        // feature float4 index

    const float* xin = (LAYER == 1) ? xext : g_h;

    int beg = g_off[n];
    int end = g_off[n + 1];

    float4 acc = make_float4(0.f, 0.f, 0.f, 0.f);
    for (int e = beg + half; e < end; e += 2) {
        int s = g_csr_src[e];
        float4 v = *reinterpret_cast<const float4*>(xin + (size_t)s * DD + (fl << 2));
        acc.x += v.x; acc.y += v.y; acc.z += v.z; acc.w += v.w;
    }
    // combine the two halves
    acc.x += __shfl_xor_sync(0xFFFFFFFF, acc.x, 16);
    acc.y += __shfl_xor_sync(0xFFFFFFFF, acc.y, 16);
    acc.z += __shfl_xor_sync(0xFFFFFFFF, acc.z, 16);
    acc.w += __shfl_xor_sync(0xFFFFFFFF, acc.w, 16);

    if (half == 0) {
        float inv = 1.0f / (float)max(end - beg, 1);
        acc.x *= inv; acc.y *= inv; acc.z *= inv; acc.w *= inv;
        *reinterpret_cast<float4*>(g_agg + (size_t)n * DD + (fl << 2)) = acc;
    }
}

// ---------------------------------------------------------------------------
// Kernel 6/8: register-tiled fused MLP (dynamic smem, ~64.3 KB/block).
//   out[n][j] = sum_k I[n][k] * Wc[k][j] + b[j]   (+ tanh for layer 1)
// where I = [agg | x] (K=128) and Wc = [W_l^T ; W_r^T] (128 x 64, k-major).
// Block tile: 64 nodes x 64 outputs; thread = 4x4 micro-tile; 2 B LDS per FMA.
// Smem layout in one dynamic blob:
//   sW: 2*64*64 floats  (32 KB)   sW[k*64 + j]
//   sI: 128*64  floats  (32 KB)   sI[k*64 + node]
//   sB: 64      floats
// ---------------------------------------------------------------------------
#define MLP_SMEM_BYTES ((2 * DD * DD + 2 * DD * DD + DD) * 4)

template <int LAYER>
__global__ __launch_bounds__(256) void mlp_kernel(
    const float* __restrict__ xext,
    const float* __restrict__ Wl,
    const float* __restrict__ bl,
    const float* __restrict__ Wr,
    float* __restrict__ outext)
{
    const float* xin = (LAYER == 1) ? xext : g_h;
    float*       out = (LAYER == 1) ? g_h : outext;

    extern __shared__ float smem[];
    float* sW = smem;                     // 8192 floats
    float* sI = smem + 2 * DD * DD;       // 8192 floats
    float* sB = sI + 2 * DD * DD;         // 64 floats

    // Stage combined weights, k-major transposed
    for (int t = threadIdx.x; t < DD * DD; t += 256) {
        int j = t >> 6, k = t & 63;
        sW[k * DD + j]        = Wl[t];
        sW[(DD + k) * DD + j] = Wr[t];
    }
    if (threadIdx.x < DD) sB[threadIdx.x] = bl[threadIdx.x];

    const int ty = threadIdx.x >> 4;       // 0..15 -> node group
    const int tx = threadIdx.x & 15;       // 0..15 -> output group
    const int n0 = ty << 2;
    const int j0 = tx << 2;
    const int ngroups = (NN + 63) / 64;    // 782

    for (int g = blockIdx.x; g < ngroups; g += gridDim.x) {
        int base = g << 6;
        __syncthreads();
        // Stage [agg|x] transposed: t = q*64 + node, q in [0,32)
        for (int t = threadIdx.x; t < 32 * 64; t += 256) {
            int q    = t >> 6;        // which float4 within the combined 128-dim row
            int node = t & 63;
            int ni   = base + node;
            float4 v = make_float4(0.f, 0.f, 0.f, 0.f);
            int kbase;
            if (q < 16) {
                kbase = q << 2;
                if (ni < NN) v = reinterpret_cast<const float4*>(g_agg + (size_t)ni * DD)[q];
            } else {
                kbase = DD + ((q - 16) << 2);
                if (ni < NN) v = reinterpret_cast<const float4*>(xin + (size_t)ni * DD)[q - 16];
            }
            sI[(kbase + 0) * DD + node] = v.x;
            sI[(kbase + 1) * DD + node] = v.y;
            sI[(kbase + 2) * DD + node] = v.z;
            sI[(kbase + 3) * DD + node] = v.w;
        }
        __syncthreads();

        float acc[4][4];
        #pragma unroll
        for (int i = 0; i < 4; i++)
            #pragma unroll
            for (int j = 0; j < 4; j++) acc[i][j] = 0.f;

        #pragma unroll 4
        for (int k = 0; k < 2 * DD; k++) {
            float4 a = *reinterpret_cast<const float4*>(sI + k * DD + n0);
            float4 w = *reinterpret_cast<const float4*>(sW + k * DD + j0);
            acc[0][0] += a.x * w.x; acc[0][1] += a.x * w.y; acc[0][2] += a.x * w.z; acc[0][3] += a.x * w.w;
            acc[1][0] += a.y * w.x; acc[1][1] += a.y * w.y; acc[1][2] += a.y * w.z; acc[1][3] += a.y * w.w;
            acc[2][0] += a.z * w.x; acc[2][1] += a.z * w.y; acc[2][2] += a.z * w.z; acc[2][3] += a.z * w.w;
            acc[3][0] += a.w * w.x; acc[3][1] += a.w * w.y; acc[3][2] += a.w * w.z; acc[3][3] += a.w * w.w;
        }

        float4 b4 = *reinterpret_cast<const float4*>(sB + j0);
        #pragma unroll
        for (int i = 0; i < 4; i++) {
            int ni = base + n0 + i;
            if (ni < NN) {
                float4 o;
                o.x = acc[i][0] + b4.x;
                o.y = acc[i][1] + b4.y;
                o.z = acc[i][2] + b4.z;
                o.w = acc[i][3] + b4.w;
                if (LAYER == 1) {
                    o.x = tanhf(o.x); o.y = tanhf(o.y);
                    o.z = tanhf(o.z); o.w = tanhf(o.w);
                }
                *reinterpret_cast<float4*>(out + (size_t)ni * DD + j0) = o;
            }
        }
    }
}

// ---------------------------------------------------------------------------
// Launch
// ---------------------------------------------------------------------------
extern "C" void kernel_launch(void* const* d_in, const int* in_sizes, int n_in,
                              void* d_out, int out_size)
{
    const float* x    = (const float*)d_in[0];
    const void*  ei   = d_in[1];
    const float* Wl1  = (const float*)d_in[2];
    const float* bl1  = (const float*)d_in[3];
    const float* Wr1  = (const float*)d_in[4];
    const float* Wl2  = (const float*)d_in[5];
    const float* bl2  = (const float*)d_in[6];
    const float* Wr2  = (const float*)d_in[7];
    float*       out  = (float*)d_out;

    // Opt in to >48KB dynamic smem (immediate API, capture-safe, idempotent)
    static int attr_done = 0;
    if (!attr_done) {
        cudaFuncSetAttribute(mlp_kernel<1>,
            cudaFuncAttributeMaxDynamicSharedMemorySize, MLP_SMEM_BYTES);
        cudaFuncSetAttribute(mlp_kernel<2>,
            cudaFuncAttributeMaxDynamicSharedMemorySize, MLP_SMEM_BYTES);
        attr_done = 1;
    }

    const int eb  = (EE + 255) / 256;          // edge-parallel blocks
    const int gb  = (NN * 32 + 255) / 256;     // gather: warp per node
    const int mb  = 444;                       // mlp: 3 resident blocks/SM

    detect_kernel<<<1, 1>>>((const int*)ei);
    zero_deg_kernel<<<(NN + 255) / 256, 256>>>();
    convert_kernel<<<eb, 256>>>(ei);
    scan_kernel<<<1, 1024>>>();
    fill_kernel<<<eb, 256>>>();
    gather_kernel<1><<<gb, 256>>>(x);
    mlp_kernel<1><<<mb, 256, MLP_SMEM_BYTES>>>(x, Wl1, bl1, Wr1, nullptr);
    gather_kernel<2><<<gb, 256>>>(nullptr);
    mlp_kernel<2><<<mb, 256, MLP_SMEM_BYTES>>>(nullptr, Wl2, bl2, Wr2, out);
}

// round 7
// speedup vs baseline: 1.7529x; 1.4874x over previous
#include <cuda_runtime.h>

#define NN 50000
#define EE 800000
#define DD 64
#define NB 196   // (NN + 255) / 256 scan blocks

// Scratch (device globals — allocation-free per harness rules)
__device__ __align__(16) float g_agg[NN * DD];   // mean-aggregated features (reused both layers)
__device__ __align__(16) float g_h[NN * DD];     // layer-1 output
__device__ int g_src32[EE];
__device__ int g_dst32[EE];
__device__ int g_deg[NN];
__device__ int g_loc[NN];       // per-element exclusive scan within its block
__device__ int g_bsum[NB];      // per-block degree sums
__device__ int g_bbase[NB];     // exclusive scan of block sums
__device__ int g_off[NN + 1];
__device__ int g_cur[NN];
__device__ int g_csr_src[EE];
__device__ int g_is64;

// ---------------------------------------------------------------------------
// Kernel 0: detect edge_index dtype (int64 => odd 32-bit words all zero).
// 64 parallel probes instead of one serial chain.
// ---------------------------------------------------------------------------
__global__ void detect_kernel(const int* __restrict__ ei32) {
    __shared__ int any_nz;
    if (threadIdx.x == 0) any_nz = 0;
    __syncthreads();
    if (ei32[2 * threadIdx.x + 1] != 0) atomicOr(&any_nz, 1);
    __syncthreads();
    if (threadIdx.x == 0) g_is64 = !any_nz;
}

// ---------------------------------------------------------------------------
// Kernel 1: zero degree counts
// ---------------------------------------------------------------------------
__global__ __launch_bounds__(256) void zero_deg_kernel() {
    int t = blockIdx.x * 256 + threadIdx.x;
    if (t < NN) g_deg[t] = 0;
}

// ---------------------------------------------------------------------------
// Kernel 2: normalize indices to int32 + integer degree histogram
// ---------------------------------------------------------------------------
__global__ __launch_bounds__(256) void convert_kernel(const void* __restrict__ ei) {
    int e = blockIdx.x * blockDim.x + threadIdx.x;
    if (e >= EE) return;
    int s, d;
    if (g_is64) {
        const long long* p = (const long long*)ei;
        s = (int)p[e];
        d = (int)p[EE + e];
    } else {
        const int* p = (const int*)ei;
        s = p[e];
        d = p[EE + e];
    }
    s = min(max(s, 0), NN - 1);
    d = min(max(d, 0), NN - 1);
    g_src32[e] = s;
    g_dst32[e] = d;
    atomicAdd(&g_deg[d], 1);
}

// ---------------------------------------------------------------------------
// Kernels 3a/3b/3c: 3-phase multi-block exclusive scan of g_deg -> g_off.
// ---------------------------------------------------------------------------
__global__ __launch_bounds__(256) void scan1_kernel() {
    __shared__ int sh[256];
    int tid = threadIdx.x;
    int i = blockIdx.x * 256 + tid;
    int v = (i < NN) ? g_deg[i] : 0;
    sh[tid] = v;
    __syncthreads();
    #pragma unroll
    for (int d = 1; d < 256; d <<= 1) {
        int t = (tid >= d) ? sh[tid - d] : 0;
        __syncthreads();
        sh[tid] += t;
        __syncthreads();
    }
    if (i < NN) g_loc[i] = sh[tid] - v;          // exclusive within block
    if (tid == 255) g_bsum[blockIdx.x] = sh[255]; // block total
}

__global__ __launch_bounds__(256) void scan2_kernel() {
    __shared__ int sh[256];
    int tid = threadIdx.x;
    int v = (tid < NB) ? g_bsum[tid] : 0;
    sh[tid] = v;
    __syncthreads();
    #pragma unroll
    for (int d = 1; d < 256; d <<= 1) {
        int t = (tid >= d) ? sh[tid - d] : 0;
        __syncthreads();
        sh[tid] += t;
        __syncthreads();
    }
    if (tid < NB) g_bbase[tid] = sh[tid] - v;    // exclusive block base
}

__global__ __launch_bounds__(256) void scan3_kernel() {
    int i = blockIdx.x * 256 + threadIdx.x;
    if (i < NN) {
        int off = g_loc[i] + g_bbase[blockIdx.x];
        g_off[i] = off;
        g_cur[i] = off;
    }
    if (i == 0) g_off[NN] = EE;
}

// ---------------------------------------------------------------------------
// Kernel 4: CSR fill (source indices grouped by destination)
// ---------------------------------------------------------------------------
__global__ __launch_bounds__(256) void fill_kernel() {
    int e = blockIdx.x * blockDim.x + threadIdx.x;
    if (e >= EE) return;
    int d = g_dst32[e];
    int pos = atomicAdd(&g_cur[d], 1);
    g_csr_src[pos] = g_src32[e];
}

// ---------------------------------------------------------------------------
// Kernel 5/7: gather-based mean aggregation. One warp per node; lanes 0-15
// handle one edge's row (float4 each), lanes 16-31 the next edge. No atomics.
// Writes mean (already divided by max(deg,1)) into g_agg.
// ---------------------------------------------------------------------------
template <int LAYER>
__global__ __launch_bounds__(256) void gather_kernel(const float* __restrict__ xext)
{
    int n = (blockIdx.x * 256 + threadIdx.x) >> 5;
    if (n >= NN) return;
    int lane = threadIdx.x & 31;
    int half = lane >> 4;        // 0 or 1
    int fl   = lane & 15;        // feature float4 index

    const float* xin = (LAYER == 1) ? xext : g_h;

    int beg = g_off[n];
    int end = g_off[n + 1];

    float4 acc = make_float4(0.f, 0.f, 0.f, 0.f);
    for (int e = beg + half; e < end; e += 2) {
        int s = g_csr_src[e];
        float4 v = *reinterpret_cast<const float4*>(xin + (size_t)s * DD + (fl << 2));
        acc.x += v.x; acc.y += v.y; acc.z += v.z; acc.w += v.w;
    }
    // combine the two halves
    acc.x += __shfl_xor_sync(0xFFFFFFFF, acc.x, 16);
    acc.y += __shfl_xor_sync(0xFFFFFFFF, acc.y, 16);
    acc.z += __shfl_xor_sync(0xFFFFFFFF, acc.z, 16);
    acc.w += __shfl_xor_sync(0xFFFFFFFF, acc.w, 16);

    if (half == 0) {
        float inv = 1.0f / (float)max(end - beg, 1);
        acc.x *= inv; acc.y *= inv; acc.z *= inv; acc.w *= inv;
        *reinterpret_cast<float4*>(g_agg + (size_t)n * DD + (fl << 2)) = acc;
    }
}

// ---------------------------------------------------------------------------
// Kernel 6/8: register-tiled fused MLP (dynamic smem, ~64.3 KB/block).
//   out[n][j] = sum_k I[n][k] * Wc[k][j] + b[j]   (+ tanh for layer 1)
// where I = [agg | x] (K=128) and Wc = [W_l^T ; W_r^T] (128 x 64, k-major).
// Block tile: 64 nodes x 64 outputs; thread = 4x4 micro-tile; 2 B LDS per FMA.
// ---------------------------------------------------------------------------
#define MLP_SMEM_BYTES ((2 * DD * DD + 2 * DD * DD + DD) * 4)

template <int LAYER>
__global__ __launch_bounds__(256) void mlp_kernel(
    const float* __restrict__ xext,
    const float* __restrict__ Wl,
    const float* __restrict__ bl,
    const float* __restrict__ Wr,
    float* __restrict__ outext)
{
    const float* xin = (LAYER == 1) ? xext : g_h;
    float*       out = (LAYER == 1) ? g_h : outext;

    extern __shared__ float smem[];
    float* sW = smem;                     // 8192 floats
    float* sI = smem + 2 * DD * DD;       // 8192 floats
    float* sB = sI + 2 * DD * DD;         // 64 floats

    // Stage combined weights, k-major transposed
    for (int t = threadIdx.x; t < DD * DD; t += 256) {
        int j = t >> 6, k = t & 63;
        sW[k * DD + j]        = Wl[t];
        sW[(DD + k) * DD + j] = Wr[t];
    }
    if (threadIdx.x < DD) sB[threadIdx.x] = bl[threadIdx.x];

    const int ty = threadIdx.x >> 4;       // 0..15 -> node group
    const int tx = threadIdx.x & 15;       // 0..15 -> output group
    const int n0 = ty << 2;
    const int j0 = tx << 2;
    const int ngroups = (NN + 63) / 64;    // 782

    for (int g = blockIdx.x; g < ngroups; g += gridDim.x) {
        int base = g << 6;
        __syncthreads();
        // Stage [agg|x] transposed: t = q*64 + node, q in [0,32)
        for (int t = threadIdx.x; t < 32 * 64; t += 256) {
            int q    = t >> 6;        // which float4 within the combined 128-dim row
            int node = t & 63;
            int ni   = base + node;
            float4 v = make_float4(0.f, 0.f, 0.f, 0.f);
            int kbase;
            if (q < 16) {
                kbase = q << 2;
                if (ni < NN) v = reinterpret_cast<const float4*>(g_agg + (size_t)ni * DD)[q];
            } else {
                kbase = DD + ((q - 16) << 2);
                if (ni < NN) v = reinterpret_cast<const float4*>(xin + (size_t)ni * DD)[q - 16];
            }
            sI[(kbase + 0) * DD + node] = v.x;
            sI[(kbase + 1) * DD + node] = v.y;
            sI[(kbase + 2) * DD + node] = v.z;
            sI[(kbase + 3) * DD + node] = v.w;
        }
        __syncthreads();

        float acc[4][4];
        #pragma unroll
        for (int i = 0; i < 4; i++)
            #pragma unroll
            for (int j = 0; j < 4; j++) acc[i][j] = 0.f;

        #pragma unroll 4
        for (int k = 0; k < 2 * DD; k++) {
            float4 a = *reinterpret_cast<const float4*>(sI + k * DD + n0);
            float4 w = *reinterpret_cast<const float4*>(sW + k * DD + j0);
            acc[0][0] += a.x * w.x; acc[0][1] += a.x * w.y; acc[0][2] += a.x * w.z; acc[0][3] += a.x * w.w;
            acc[1][0] += a.y * w.x; acc[1][1] += a.y * w.y; acc[1][2] += a.y * w.z; acc[1][3] += a.y * w.w;
            acc[2][0] += a.z * w.x; acc[2][1] += a.z * w.y; acc[2][2] += a.z * w.z; acc[2][3] += a.z * w.w;
            acc[3][0] += a.w * w.x; acc[3][1] += a.w * w.y; acc[3][2] += a.w * w.z; acc[3][3] += a.w * w.w;
        }

        float4 b4 = *reinterpret_cast<const float4*>(sB + j0);
        #pragma unroll
        for (int i = 0; i < 4; i++) {
            int ni = base + n0 + i;
            if (ni < NN) {
                float4 o;
                o.x = acc[i][0] + b4.x;
                o.y = acc[i][1] + b4.y;
                o.z = acc[i][2] + b4.z;
                o.w = acc[i][3] + b4.w;
                if (LAYER == 1) {
                    o.x = tanhf(o.x); o.y = tanhf(o.y);
                    o.z = tanhf(o.z); o.w = tanhf(o.w);
                }
                *reinterpret_cast<float4*>(out + (size_t)ni * DD + j0) = o;
            }
        }
    }
}

// ---------------------------------------------------------------------------
// Launch
// ---------------------------------------------------------------------------
extern "C" void kernel_launch(void* const* d_in, const int* in_sizes, int n_in,
                              void* d_out, int out_size)
{
    const float* x    = (const float*)d_in[0];
    const void*  ei   = d_in[1];
    const float* Wl1  = (const float*)d_in[2];
    const float* bl1  = (const float*)d_in[3];
    const float* Wr1  = (const float*)d_in[4];
    const float* Wl2  = (const float*)d_in[5];
    const float* bl2  = (const float*)d_in[6];
    const float* Wr2  = (const float*)d_in[7];
    float*       out  = (float*)d_out;

    // Opt in to >48KB dynamic smem (immediate API, capture-safe, idempotent)
    static int attr_done = 0;
    if (!attr_done) {
        cudaFuncSetAttribute(mlp_kernel<1>,
            cudaFuncAttributeMaxDynamicSharedMemorySize, MLP_SMEM_BYTES);
        cudaFuncSetAttribute(mlp_kernel<2>,
            cudaFuncAttributeMaxDynamicSharedMemorySize, MLP_SMEM_BYTES);
        attr_done = 1;
    }

    const int eb  = (EE + 255) / 256;          // edge-parallel blocks
    const int gb  = (NN * 32 + 255) / 256;     // gather: warp per node
    const int mb  = 444;                       // mlp: 3 resident blocks/SM

    detect_kernel<<<1, 64>>>((const int*)ei);
    zero_deg_kernel<<<NB, 256>>>();
    convert_kernel<<<eb, 256>>>(ei);
    scan1_kernel<<<NB, 256>>>();
    scan2_kernel<<<1, 256>>>();
    scan3_kernel<<<NB, 256>>>();
    fill_kernel<<<eb, 256>>>();
    gather_kernel<1><<<gb, 256>>>(x);
    mlp_kernel<1><<<mb, 256, MLP_SMEM_BYTES>>>(x, Wl1, bl1, Wr1, nullptr);
    gather_kernel<2><<<gb, 256>>>(nullptr);
    mlp_kernel<2><<<mb, 256, MLP_SMEM_BYTES>>>(nullptr, Wl2, bl2, Wr2, out);
}